// round 7
// baseline (speedup 1.0000x reference)
#include <cuda_runtime.h>

// ConceptGaussians gather:
//   means[b, d]    = mean[d, labels[b, d]]
//   log_vars[b, d] = log_var[d, labels[b, d]]
// labels: [B, 8] int32, mean/log_var: [8, 64] f32.
// Output: means (B*8 floats) then log_vars (B*8 floats).
//
// One thread = one full row of 8 labels:
//   2x LDG.128 (labels, front-batched) -> 8x LDS.64 (float2 table gather)
//   -> 2x STG.128 per output stream. Raises MLP and amortizes index math.

#define N_DOMAINS 8
#define MAX_CONCEPTS 64
#define TBL_ELEMS (N_DOMAINS * MAX_CONCEPTS)   // 512

__global__ void __launch_bounds__(256)
concept_gather_row_kernel(const int4* __restrict__ labels4,
                          const float* __restrict__ mean,
                          const float* __restrict__ log_var,
                          float4* __restrict__ out_mean4,
                          float4* __restrict__ out_lv4,
                          int nrows)
{
    // Interleaved table: one LDS.64 yields (mean, log_var) for a (domain, idx).
    __shared__ float2 tbl[TBL_ELEMS];
    for (int k = threadIdx.x; k < TBL_ELEMS; k += blockDim.x) {
        tbl[k] = make_float2(mean[k], log_var[k]);
    }
    __syncthreads();

    int b = blockIdx.x * blockDim.x + threadIdx.x;
    if (b >= nrows) return;

    // Front-batch both label loads (MLP=2 LDG.128 in flight).
    int4 L0 = labels4[2 * b];
    int4 L1 = labels4[2 * b + 1];

    const int M = MAX_CONCEPTS - 1;
    float2 g0 = tbl[0 * MAX_CONCEPTS + (L0.x & M)];
    float2 g1 = tbl[1 * MAX_CONCEPTS + (L0.y & M)];
    float2 g2 = tbl[2 * MAX_CONCEPTS + (L0.z & M)];
    float2 g3 = tbl[3 * MAX_CONCEPTS + (L0.w & M)];
    float2 g4 = tbl[4 * MAX_CONCEPTS + (L1.x & M)];
    float2 g5 = tbl[5 * MAX_CONCEPTS + (L1.y & M)];
    float2 g6 = tbl[6 * MAX_CONCEPTS + (L1.z & M)];
    float2 g7 = tbl[7 * MAX_CONCEPTS + (L1.w & M)];

    out_mean4[2 * b]     = make_float4(g0.x, g1.x, g2.x, g3.x);
    out_mean4[2 * b + 1] = make_float4(g4.x, g5.x, g6.x, g7.x);
    out_lv4[2 * b]       = make_float4(g0.y, g1.y, g2.y, g3.y);
    out_lv4[2 * b + 1]   = make_float4(g4.y, g5.y, g6.y, g7.y);
}

extern "C" void kernel_launch(void* const* d_in, const int* in_sizes, int n_in,
                              void* d_out, int out_size)
{
    const int*   labels  = (const int*)  d_in[0];   // [B, 8] int32
    const float* mean    = (const float*)d_in[1];   // [8, 64]
    const float* log_var = (const float*)d_in[2];   // [8, 64]

    int n_elems = in_sizes[0];          // B * 8
    int nrows   = n_elems >> 3;         // B

    float* out      = (float*)d_out;
    float* out_mean = out;              // first half: means
    float* out_lv   = out + n_elems;    // second half: log_vars

    const int threads = 256;
    int blocks = (nrows + threads - 1) / threads;

    concept_gather_row_kernel<<<blocks, threads>>>(
        (const int4*)labels, mean, log_var,
        (float4*)out_mean, (float4*)out_lv, nrows);
}

// round 10
// speedup vs baseline: 1.0284x; 1.0284x over previous
#include <cuda_runtime.h>

// ConceptGaussians gather:
//   means[b, d]    = mean[d, labels[b, d]]
//   log_vars[b, d] = log_var[d, labels[b, d]]
// labels: [B, 8] int32, mean/log_var: [8, 64] f32.
// Output: means (B*8 floats) then log_vars (B*8 floats).
//
// Mapping: one thread = two WARP-STRIDED int4 chunks (chunk c and c+32).
//  - both label LDG.128 are independent (front-batched, MLP=2)
//  - every LDG/STG stays perfectly coalesced (contiguous 512B per warp op)
//  - table gathers via float2-interleaved smem (1 LDS.64 = mean+log_var)

#define N_DOMAINS 8
#define MAX_CONCEPTS 64
#define TBL_ELEMS (N_DOMAINS * MAX_CONCEPTS)   // 512

__global__ void __launch_bounds__(256)
concept_gather_ws_kernel(const int4* __restrict__ labels4,
                         const float* __restrict__ mean,
                         const float* __restrict__ log_var,
                         float4* __restrict__ out_mean4,
                         float4* __restrict__ out_lv4,
                         int n4)
{
    __shared__ float2 tbl[TBL_ELEMS];
    for (int k = threadIdx.x; k < TBL_ELEMS; k += blockDim.x) {
        tbl[k] = make_float2(mean[k], log_var[k]);
    }
    __syncthreads();

    int tid  = blockIdx.x * blockDim.x + threadIdx.x;
    int wid  = tid >> 5;
    int lane = tid & 31;

    // Warp handles 64 consecutive chunks; thread gets chunk c0 and c0+32.
    int c0 = wid * 64 + lane;
    int c1 = c0 + 32;
    if (c0 >= n4) return;

    const int M = MAX_CONCEPTS - 1;

    // Front-batch both independent label loads.
    int4 L0 = labels4[c0];
    int4 L1 = (c1 < n4) ? labels4[c1] : make_int4(0, 0, 0, 0);

    // Chunk c covers domains dbase..dbase+3, dbase = (4c) & 7.
    int d0 = (c0 << 2) & (N_DOMAINS - 1);
    int d1 = (c1 << 2) & (N_DOMAINS - 1);
    const float2* r0 = tbl + d0 * MAX_CONCEPTS;
    const float2* r1 = tbl + d1 * MAX_CONCEPTS;

    float2 a0 = r0[0 * MAX_CONCEPTS + (L0.x & M)];
    float2 b0 = r0[1 * MAX_CONCEPTS + (L0.y & M)];
    float2 g0 = r0[2 * MAX_CONCEPTS + (L0.z & M)];
    float2 h0 = r0[3 * MAX_CONCEPTS + (L0.w & M)];
    float2 a1 = r1[0 * MAX_CONCEPTS + (L1.x & M)];
    float2 b1 = r1[1 * MAX_CONCEPTS + (L1.y & M)];
    float2 g1 = r1[2 * MAX_CONCEPTS + (L1.z & M)];
    float2 h1 = r1[3 * MAX_CONCEPTS + (L1.w & M)];

    out_mean4[c0] = make_float4(a0.x, b0.x, g0.x, h0.x);
    out_lv4[c0]   = make_float4(a0.y, b0.y, g0.y, h0.y);
    if (c1 < n4) {
        out_mean4[c1] = make_float4(a1.x, b1.x, g1.x, h1.x);
        out_lv4[c1]   = make_float4(a1.y, b1.y, g1.y, h1.y);
    }
}

extern "C" void kernel_launch(void* const* d_in, const int* in_sizes, int n_in,
                              void* d_out, int out_size)
{
    const int*   labels  = (const int*)  d_in[0];   // [B, 8] int32
    const float* mean    = (const float*)d_in[1];   // [8, 64]
    const float* log_var = (const float*)d_in[2];   // [8, 64]

    int n_elems = in_sizes[0];          // B * 8
    int n4      = n_elems >> 2;         // int4 chunks

    float* out      = (float*)d_out;
    float* out_mean = out;              // first half: means
    float* out_lv   = out + n_elems;    // second half: log_vars

    const int threads = 256;
    // each thread covers 2 chunks
    int nthreads_needed = (n4 + 1) / 2;
    int blocks = (nthreads_needed + threads - 1) / threads;

    concept_gather_ws_kernel<<<blocks, threads>>>(
        (const int4*)labels, mean, log_var,
        (float4*)out_mean, (float4*)out_lv, n4);
}